// round 15
// baseline (speedup 1.0000x reference)
#include <cuda_runtime.h>
#include <cstdint>

// Problem constants (fixed by the reference)
#define NUM_VERTS 6890
#define NUM_FACES 13776
#define HH 1024
#define WW 1024
#define NB 16
#define HW (HH * WW)

#define CHUNKS 2
#define PX_PER_CHUNK (HW / CHUNKS)            // 524288 pixels
#define V4_PER_CHUNK (PX_PER_CHUNK * 3 / 4)   // 393216 float4 per chunk per slice

// Pre-packed per-face vertex attributes: 3 float4 (xyz + pad) per face.
// 13776 * 3 * 16 B = 661 KB -> L2-resident. __device__ global = allowed scratch.
__device__ float4 g_fattr[NUM_FACES * 3];

// ---------------------------------------------------------------------------
// Kernel P: pack verts[0] into face-major float4 table.
// One thread per FACE-VERTEX (41328 threads): coalesced index load, one 12B
// gather, one float4 store. 162 blocks -> covers all SMs.
// ---------------------------------------------------------------------------
__global__ __launch_bounds__(256) void uvrender_prepack(
    const float* __restrict__ verts,   // (16, 6890, 3) fp32; batch 0 only
    const int*   __restrict__ faces)   // (13776, 3) int32
{
    const int idx = blockIdx.x * blockDim.x + threadIdx.x;   // face*3 + corner
    if (idx >= NUM_FACES * 3) return;

    int v = __ldg(faces + idx);                   // coalesced
    v = max(0, min(v, NUM_VERTS - 1));            // defensive, dead in practice

    const float* a = verts + v * 3;
    g_fattr[idx] = make_float4(a[0], a[1], a[2], 0.f);
}

// ---------------------------------------------------------------------------
// Kernel A: compute interpolated attributes for one pixel half, write
// slice 0 only. 4 pixels/thread -> 12 float4 gathers + 3 float4 stores.
// 512 blocks/chunk keeps ~27 warps/SM so gather latency stays hidden.
// ---------------------------------------------------------------------------
__global__ __launch_bounds__(256) void uvrender_compute(
    const int*   __restrict__ pix,     // (1024, 1024) int32
    const float* __restrict__ bary,    // (1024, 1024, 3) fp32
    float* __restrict__ out,           // slice 0 of (16, 1024, 1024, 3) fp32
    int p_base)
{
    const int t = blockIdx.x * blockDim.x + threadIdx.x;
    const int p0 = p_base + t * 4;

    const int4 pv = *reinterpret_cast<const int4*>(pix + p0);
    int pf[4] = {pv.x, pv.y, pv.z, pv.w};

    const float4 b0 = __ldcs(reinterpret_cast<const float4*>(bary + (size_t)p0 * 3));
    const float4 b1 = __ldcs(reinterpret_cast<const float4*>(bary + (size_t)p0 * 3 + 4));
    const float4 b2 = __ldcs(reinterpret_cast<const float4*>(bary + (size_t)p0 * 3 + 8));
    float bc[12] = {b0.x, b0.y, b0.z, b0.w,
                    b1.x, b1.y, b1.z, b1.w,
                    b2.x, b2.y, b2.z, b2.w};

    float r[12];
#pragma unroll
    for (int i = 0; i < 4; i++) {
        float ox = 0.f, oy = 0.f, oz = 0.f;
        int f = pf[i];
        if (f >= 0) {
            f = min(f, NUM_FACES - 1);            // defensive, dead in practice
            const float4 fa0 = __ldg(&g_fattr[f * 3 + 0]);
            const float4 fa1 = __ldg(&g_fattr[f * 3 + 1]);
            const float4 fa2 = __ldg(&g_fattr[f * 3 + 2]);
            const float w0 = bc[i * 3 + 0];
            const float w1 = bc[i * 3 + 1];
            const float w2 = bc[i * 3 + 2];
            ox = w0 * fa0.x + w1 * fa1.x + w2 * fa2.x;
            oy = w0 * fa0.y + w1 * fa1.y + w2 * fa2.y;
            oz = w0 * fa0.z + w1 * fa1.z + w2 * fa2.z;
        }
        r[i * 3 + 0] = ox;
        r[i * 3 + 1] = oy;
        r[i * 3 + 2] = oz;
    }

    float4* dst = reinterpret_cast<float4*>(out + (size_t)p0 * 3);
    dst[0] = make_float4(r[0], r[1], r[2], r[3]);
    dst[1] = make_float4(r[4], r[5], r[6], r[7]);
    dst[2] = make_float4(r[8], r[9], r[10], r[11]);
}

// ---------------------------------------------------------------------------
// Kernel B: broadcast one half of slice 0 -> slices 1..15. Pure streaming
// copy; source is L2-resident (just written by the matching compute chunk).
// ---------------------------------------------------------------------------
__global__ __launch_bounds__(256) void uvrender_broadcast(
    float* __restrict__ out, int v4_base)
{
    const int idx = v4_base + blockIdx.x * blockDim.x + threadIdx.x;

    const float4 v = __ldg(reinterpret_cast<const float4*>(out) + idx);

#pragma unroll
    for (int n = 1; n < NB; n++) {
        __stcs(reinterpret_cast<float4*>(out + (size_t)n * HW * 3) + idx, v);
    }
}

extern "C" void kernel_launch(void* const* d_in, const int* in_sizes, int n_in,
                              void* d_out, int out_size)
{
    const float* verts = (const float*)d_in[0];  // (16, 6890, 3) f32
    const int*   faces = (const int*)d_in[1];    // (13776, 3) i32
    const int*   pix   = (const int*)d_in[2];    // (1024, 1024) i32
    const float* bary  = (const float*)d_in[3];  // (1024, 1024, 3) f32
    float*       out   = (float*)d_out;          // (16, 1024, 1024, 3) f32

    // Lazily-created side stream + events (host objects only; no device
    // allocation; identical launch topology on every call).
    static cudaStream_t s1 = nullptr;
    static cudaEvent_t evC[CHUNKS] = {};
    static cudaEvent_t evJoin = nullptr;
    if (s1 == nullptr) {
        cudaStreamCreateWithFlags(&s1, cudaStreamNonBlocking);
        for (int c = 0; c < CHUNKS; c++)
            cudaEventCreateWithFlags(&evC[c], cudaEventDisableTiming);
        cudaEventCreateWithFlags(&evJoin, cudaEventDisableTiming);
    }

    const int threads = 256;

    // Prepack on the main stream (compute chunks depend on it in-order).
    const int thrP = NUM_FACES * 3;              // 41328
    uvrender_prepack<<<(thrP + threads - 1) / threads, threads>>>(verts, faces);

    // Pipeline: compute(c) on main stream; broadcast(c) on s1 after event.
    // compute(1) overlaps broadcast(0).
    const int blkA = PX_PER_CHUNK / 4 / threads;   // 512 blocks per chunk
    const int blkB = V4_PER_CHUNK / threads;       // 1536 blocks per chunk
    for (int c = 0; c < CHUNKS; c++) {
        uvrender_compute<<<blkA, threads>>>(pix, bary, out, c * PX_PER_CHUNK);
        cudaEventRecord(evC[c], 0);
        cudaStreamWaitEvent(s1, evC[c], 0);
        uvrender_broadcast<<<blkB, threads, 0, s1>>>(out, c * V4_PER_CHUNK);
    }

    // Join s1 back into the main stream so the harness sees completion.
    cudaEventRecord(evJoin, s1);
    cudaStreamWaitEvent(0, evJoin, 0);
}

// round 16
// speedup vs baseline: 1.4279x; 1.4279x over previous
#include <cuda_runtime.h>
#include <cstdint>

// Problem constants (fixed by the reference)
#define NUM_VERTS 6890
#define NUM_FACES 13776
#define HH 1024
#define WW 1024
#define NB 16
#define HW (HH * WW)
#define NV4 (HW * 3 / 4)   // 786432 float4 elements per slice

// Pre-packed per-face vertex attributes: 3 float4 (xyz + pad) per face.
// 13776 * 3 * 16 B = 661 KB -> L2-resident. __device__ global = allowed scratch.
__device__ float4 g_fattr[NUM_FACES * 3];

// ---------------------------------------------------------------------------
// Kernel P: pack verts[0] into face-major float4 table.
// One thread per FACE-VERTEX (41328 threads): coalesced index load, one 12B
// gather, one float4 store. 162 blocks -> covers all SMs, one short
// dependency chain per thread. Measured ~1.5 us.
// ---------------------------------------------------------------------------
__global__ __launch_bounds__(256) void uvrender_prepack(
    const float* __restrict__ verts,   // (16, 6890, 3) fp32; batch 0 only
    const int*   __restrict__ faces)   // (13776, 3) int32
{
    const int idx = blockIdx.x * blockDim.x + threadIdx.x;   // face*3 + corner
    if (idx >= NUM_FACES * 3) return;

    int v = __ldg(faces + idx);                   // coalesced
    v = max(0, min(v, NUM_VERTS - 1));            // defensive, dead in practice

    const float* a = verts + v * 3;
    g_fattr[idx] = make_float4(a[0], a[1], a[2], 0.f);
}

// ---------------------------------------------------------------------------
// Kernel A: compute interpolated attributes ONCE (full grid), write slice 0.
// 4 pixels/thread -> 12 float4 table gathers + 3 float4 stores.
// L1-wavefront-bound on the random gathers; needs the full machine
// (1024 blocks) to hide latency. Measured ~9.6 us in isolation.
// ---------------------------------------------------------------------------
__global__ __launch_bounds__(256) void uvrender_compute(
    const int*   __restrict__ pix,     // (1024, 1024) int32
    const float* __restrict__ bary,    // (1024, 1024, 3) fp32
    float* __restrict__ out)           // slice 0 of (16, 1024, 1024, 3) fp32
{
    const int t = blockIdx.x * blockDim.x + threadIdx.x;
    const int p0 = t * 4;
    if (p0 >= HW) return;

    const int4 pv = *reinterpret_cast<const int4*>(pix + p0);
    int pf[4] = {pv.x, pv.y, pv.z, pv.w};

    const float4 b0 = __ldcs(reinterpret_cast<const float4*>(bary + (size_t)p0 * 3));
    const float4 b1 = __ldcs(reinterpret_cast<const float4*>(bary + (size_t)p0 * 3 + 4));
    const float4 b2 = __ldcs(reinterpret_cast<const float4*>(bary + (size_t)p0 * 3 + 8));
    float bc[12] = {b0.x, b0.y, b0.z, b0.w,
                    b1.x, b1.y, b1.z, b1.w,
                    b2.x, b2.y, b2.z, b2.w};

    float r[12];
#pragma unroll
    for (int i = 0; i < 4; i++) {
        float ox = 0.f, oy = 0.f, oz = 0.f;
        int f = pf[i];
        if (f >= 0) {
            f = min(f, NUM_FACES - 1);            // defensive, dead in practice
            const float4 fa0 = __ldg(&g_fattr[f * 3 + 0]);
            const float4 fa1 = __ldg(&g_fattr[f * 3 + 1]);
            const float4 fa2 = __ldg(&g_fattr[f * 3 + 2]);
            const float w0 = bc[i * 3 + 0];
            const float w1 = bc[i * 3 + 1];
            const float w2 = bc[i * 3 + 2];
            ox = w0 * fa0.x + w1 * fa1.x + w2 * fa2.x;
            oy = w0 * fa0.y + w1 * fa1.y + w2 * fa2.y;
            oz = w0 * fa0.z + w1 * fa1.z + w2 * fa2.z;
        }
        r[i * 3 + 0] = ox;
        r[i * 3 + 1] = oy;
        r[i * 3 + 2] = oz;
    }

    float4* dst = reinterpret_cast<float4*>(out + (size_t)p0 * 3);
    dst[0] = make_float4(r[0], r[1], r[2], r[3]);
    dst[1] = make_float4(r[4], r[5], r[6], r[7]);
    dst[2] = make_float4(r[8], r[9], r[10], r[11]);
}

// ---------------------------------------------------------------------------
// Kernel B: broadcast slice 0 -> slices 1..15 (full slice). Pure streaming
// copy; source is L2-resident after kernel A. Measured ~31.6 us = LTS cap.
// ---------------------------------------------------------------------------
__global__ __launch_bounds__(256) void uvrender_broadcast(
    float* __restrict__ out)
{
    const int idx = blockIdx.x * blockDim.x + threadIdx.x;
    if (idx >= NV4) return;

    const float4 v = __ldg(reinterpret_cast<const float4*>(out) + idx);

#pragma unroll
    for (int n = 1; n < NB; n++) {
        __stcs(reinterpret_cast<float4*>(out + (size_t)n * HW * 3) + idx, v);
    }
}

extern "C" void kernel_launch(void* const* d_in, const int* in_sizes, int n_in,
                              void* d_out, int out_size)
{
    const float* verts = (const float*)d_in[0];  // (16, 6890, 3) f32
    const int*   faces = (const int*)d_in[1];    // (13776, 3) i32
    const int*   pix   = (const int*)d_in[2];    // (1024, 1024) i32
    const float* bary  = (const float*)d_in[3];  // (1024, 1024, 3) f32
    float*       out   = (float*)d_out;          // (16, 1024, 1024, 3) f32

    const int threads = 256;

    const int thrP = NUM_FACES * 3;              // 41328
    uvrender_prepack<<<(thrP + threads - 1) / threads, threads>>>(verts, faces);

    const int thrA = HW / 4;                     // 262144
    uvrender_compute<<<(thrA + threads - 1) / threads, threads>>>(pix, bary, out);

    uvrender_broadcast<<<(NV4 + threads - 1) / threads, threads>>>(out);
}